// round 14
// baseline (speedup 1.0000x reference)
#include <cuda_runtime.h>
#include <cuda_bf16.h>
#include <cstdint>
#include <cstddef>

#define BATCH  4
#define LQN    4096
#define LKN    4096
#define EMB    1024
#define NH     16
#define HD     64
#define BHN    64
#define NCH2   16       // phase1 chunks
#define KCH    256      // k rows per phase1 CTA
#define KT1    32       // k rows per phase1 tile
#define SP2    72       // phase2 plane stride (u16)
#define OSTR   68       // phase2 output staging stride (floats; 272B = 16B-mult)

typedef unsigned long long u64;
typedef unsigned int u32;
typedef unsigned short u16;

// Scratch (static __device__ — no allocation)
__device__ float g_kvp[(size_t)NCH2*BHN*HD*HD];
__device__ float g_ksp[(size_t)NCH2*BHN*HD];
__device__ float g_ks [(size_t)BHN*HD];
__device__ u16   g_kvbh[(size_t)BHN*HD*HD];   // kv^T hi bf16 [bh][e][d]
__device__ u16   g_kvbl[(size_t)BHN*HD*HD];

// ---------------- helpers ----------------
__device__ __forceinline__ float phi_sig(float x){
    float t, r;
    float a = fmaf(x, -0.8732633f, 5.9179351f);
    asm("ex2.approx.ftz.f32 %0, %1;" : "=f"(t) : "f"(a));
    asm("rcp.approx.ftz.f32 %0, %1;" : "=f"(r) : "f"(1.0f + t));
    return r;
}
__device__ __forceinline__ float rcpf(float x){
    float r; asm("rcp.approx.ftz.f32 %0, %1;" : "=f"(r) : "f"(x)); return r;
}
__device__ __forceinline__ u32 sm32(const void* p){
    u32 a; asm("{ .reg .u64 t; cvta.to.shared.u64 t, %1; cvt.u32.u64 %0, t; }" : "=r"(a) : "l"(p));
    return a;
}
__device__ __forceinline__ void ldm4(u32* r, u32 addr){
    asm volatile("ldmatrix.sync.aligned.m8n8.x4.shared.b16 {%0,%1,%2,%3}, [%4];"
        : "=r"(r[0]),"=r"(r[1]),"=r"(r[2]),"=r"(r[3]) : "r"(addr));
}
__device__ __forceinline__ void ldm4t(u32* r, u32 addr){
    asm volatile("ldmatrix.sync.aligned.m8n8.x4.trans.shared.b16 {%0,%1,%2,%3}, [%4];"
        : "=r"(r[0]),"=r"(r[1]),"=r"(r[2]),"=r"(r[3]) : "r"(addr));
}
__device__ __forceinline__ void mma_bf16(float* c, const u32* a, const u32* b){
    asm volatile("mma.sync.aligned.m16n8k16.row.col.f32.bf16.bf16.f32 "
        "{%0,%1,%2,%3}, {%4,%5,%6,%7}, {%8,%9}, {%0,%1,%2,%3};"
        : "+f"(c[0]),"+f"(c[1]),"+f"(c[2]),"+f"(c[3])
        : "r"(a[0]),"r"(a[1]),"r"(a[2]),"r"(a[3]), "r"(b[0]),"r"(b[1]));
}
__device__ __forceinline__ void mma_b(float* c, const u32* a, u32 b0, u32 b1){
    asm volatile("mma.sync.aligned.m16n8k16.row.col.f32.bf16.bf16.f32 "
        "{%0,%1,%2,%3}, {%4,%5,%6,%7}, {%8,%9}, {%0,%1,%2,%3};"
        : "+f"(c[0]),"+f"(c[1]),"+f"(c[2]),"+f"(c[3])
        : "r"(a[0]),"r"(a[1]),"r"(a[2]),"r"(a[3]), "r"(b0),"r"(b1));
}
__device__ __forceinline__ void hilo2(float x0, float x1, u32& hp, u32& lp){
    __nv_bfloat16 h0 = __float2bfloat16_rn(x0);
    __nv_bfloat16 h1 = __float2bfloat16_rn(x1);
    float l0 = x0 - __bfloat162float(h0);
    float l1 = x1 - __bfloat162float(h1);
    __nv_bfloat16 q0 = __float2bfloat16_rn(l0);
    __nv_bfloat16 q1 = __float2bfloat16_rn(l1);
    hp = (u32)__bfloat16_as_ushort(h0) | ((u32)__bfloat16_as_ushort(h1) << 16);
    lp = (u32)__bfloat16_as_ushort(q0) | ((u32)__bfloat16_as_ushort(q1) << 16);
}
__device__ __forceinline__ void pack_hilo4(float p0,float p1,float p2,float p3,
                                           u64& hv, u64& lv){
    u32 h01, l01, h23, l23;
    hilo2(p0, p1, h01, l01);
    hilo2(p2, p3, h23, l23);
    hv = ((u64)h23 << 32) | (u64)h01;
    lv = ((u64)l23 << 32) | (u64)l01;
}

// ============================================================================
// Phase 1 (VERIFIED R13): kv = phi(K)^T @ V, dual k-major swizzled planes,
// trans-ldmatrix A and B. grid (BHN, NCH2), 128 threads.
// ============================================================================
__global__ void __launch_bounds__(128, 4) la_phase1(const float* __restrict__ K,
                                                    const float* __restrict__ V){
    __shared__ __align__(16) unsigned char plK[2][8192];   // hi@0, lo@4096
    __shared__ __align__(16) unsigned char plV[2][8192];
    __shared__ float ksst[8][64];

    const int tid  = threadIdx.x;
    const int lane = tid & 31;
    const int wid  = tid >> 5;
    const int bh   = blockIdx.x;
    const int ck   = blockIdx.y;
    const int b    = bh >> 4;
    const int h    = bh & 15;
    const int k0   = ck * KCH;

    const float* Kb = K + (size_t)b*LKN*EMB + (size_t)h*HD;
    const float* Vb = V + (size_t)b*LKN*EMB + (size_t)h*HD;

    const int rg = tid >> 4;
    const int dq = tid & 15;
    const u32 stoff = (u32)(((((dq>>1) ^ rg) & 7) << 4) + (dq&1)*8);

    const int j  = lane & 7;
    const int g3 = lane >> 3;
    const int rowpart = ((g3>>1)*8 + j)*128;
    const u32 oA = (u32)(rowpart + ((((wid*2 + (g3&1)) ^ j) & 7) << 4));
    u32 oBV[4];
    #pragma unroll
    for(int g2=0; g2<4; g2++)
        oBV[g2] = (u32)(rowpart + ((((g2*2 + (g3&1)) ^ j) & 7) << 4));

    const u32 kbase = sm32(plK);
    const u32 vbase = sm32(plV);

    float acc[8][4];
    #pragma unroll
    for(int i=0;i<8;i++){ acc[i][0]=acc[i][1]=acc[i][2]=acc[i][3]=0.f; }
    float ks4[4] = {0.f,0.f,0.f,0.f};

    float4 kf[4], vf[4];
    #pragma unroll
    for(int i=0;i<4;i++){
        kf[i] = *(const float4*)(Kb + (size_t)(k0 + rg + i*8)*EMB + dq*4);
        vf[i] = *(const float4*)(Vb + (size_t)(k0 + rg + i*8)*EMB + dq*4);
    }

    int st = 0;
    const int NT = KCH / KT1;
    for(int t=0; t<NT; t++){
        __syncthreads();
        {
            unsigned char* ks_ = &plK[st][0];
            unsigned char* vs_ = &plV[st][0];
            #pragma unroll
            for(int i=0;i<4;i++){
                const u32 off = (u32)((rg + i*8)*128) + stoff;
                float p0=phi_sig(kf[i].x), p1=phi_sig(kf[i].y),
                      p2=phi_sig(kf[i].z), p3=phi_sig(kf[i].w);
                ks4[0]+=p0; ks4[1]+=p1; ks4[2]+=p2; ks4[3]+=p3;
                u64 hv, lv;
                pack_hilo4(p0,p1,p2,p3, hv, lv);
                *(u64*)(ks_ + off)        = hv;
                *(u64*)(ks_ + 4096 + off) = lv;
                pack_hilo4(vf[i].x, vf[i].y, vf[i].z, vf[i].w, hv, lv);
                *(u64*)(vs_ + off)        = hv;
                *(u64*)(vs_ + 4096 + off) = lv;
            }
        }
        __syncthreads();
        if(t+1 < NT){
            const int kb = k0 + (t+1)*KT1;
            #pragma unroll
            for(int i=0;i<4;i++){
                kf[i] = *(const float4*)(Kb + (size_t)(kb + rg + i*8)*EMB + dq*4);
                vf[i] = *(const float4*)(Vb + (size_t)(kb + rg + i*8)*EMB + dq*4);
            }
        }
        #pragma unroll
        for(int s=0; s<2; s++){
            const u32 khi = kbase + (u32)(st*8192 + s*2048);
            const u32 vhi = vbase + (u32)(st*8192 + s*2048);
            u32 ah[4], al[4];
            ldm4t(ah, khi + oA);
            ldm4t(al, khi + 4096u + oA);
            #pragma unroll
            for(int g2=0; g2<4; g2++){
                u32 bh4[4], bl4[4];
                ldm4t(bh4, vhi + oBV[g2]);
                ldm4t(bl4, vhi + 4096u + oBV[g2]);
                mma_b(acc[g2*2],   ah, bh4[0], bh4[2]);
                mma_b(acc[g2*2],   al, bh4[0], bh4[2]);
                mma_b(acc[g2*2],   ah, bl4[0], bl4[2]);
                mma_b(acc[g2*2+1], ah, bh4[1], bh4[3]);
                mma_b(acc[g2*2+1], al, bh4[1], bh4[3]);
                mma_b(acc[g2*2+1], ah, bl4[1], bl4[3]);
            }
        }
        st ^= 1;
    }

    {
        float* gp = g_kvp + ((size_t)(ck*BHN + bh))*HD*HD;
        const int d0 = wid*16;
        const int g  = lane >> 2;
        const int tg = lane & 3;
        const int r0 = d0 + g, r1 = r0 + 8;
        #pragma unroll
        for(int n=0;n<8;n++){
            const int e = n*8 + tg*2;
            *(float2*)(gp + r0*HD + e) = make_float2(acc[n][0], acc[n][1]);
            *(float2*)(gp + r1*HD + e) = make_float2(acc[n][2], acc[n][3]);
        }
    }
    #pragma unroll
    for(int i=0;i<4;i++) ksst[rg][dq*4+i] = ks4[i];
    __syncthreads();
    if(tid < HD){
        float s = 0.f;
        #pragma unroll
        for(int i=0;i<8;i++) s += ksst[i][tid];
        g_ksp[(size_t)(ck*BHN + bh)*HD + tid] = s;
    }
}

// ============================================================================
// Reduce (VERIFIED R6)
// ============================================================================
__global__ void __launch_bounds__(256) la_reduce(){
    const int bh  = blockIdx.x;
    const int tid = threadIdx.x;
    for(int idx = tid; idx < HD*HD; idx += 256){
        float s = 0.f;
        #pragma unroll
        for(int c=0;c<NCH2;c++)
            s += g_kvp[((size_t)c*BHN + bh)*HD*HD + idx];
        const int d = idx >> 6, e = idx & 63;
        __nv_bfloat16 hi = __float2bfloat16_rn(s);
        __nv_bfloat16 lo = __float2bfloat16_rn(s - __bfloat162float(hi));
        g_kvbh[(size_t)bh*HD*HD + e*HD + d] = __bfloat16_as_ushort(hi);
        g_kvbl[(size_t)bh*HD*HD + e*HD + d] = __bfloat16_as_ushort(lo);
    }
    if(tid < HD){
        float s = 0.f;
        #pragma unroll
        for(int c=0;c<NCH2;c++)
            s += g_ksp[(size_t)(c*BHN + bh)*HD + tid];
        g_ks[(size_t)bh*HD + tid] = s;
    }
}

// ============================================================================
// Phase 2: verified R11 conversion/mma + NEW staged coalesced epilogue.
// After mma, q planes are dead -> overlay float stage[128][OSTR].
// ============================================================================
extern __shared__ u16 smp2[];
__global__ void __launch_bounds__(128, 4) la_phase2(const float* __restrict__ Q,
                                                    float* __restrict__ out){
    u16* qh  = smp2;
    u16* ql  = qh  + 128*SP2;
    u16* kvh = ql  + 128*SP2;
    u16* kvl = kvh + 64*SP2;
    float* sden = (float*)(kvl + 64*SP2);
    float* sks  = sden + 128;

    const int tid  = threadIdx.x;
    const int lane = tid & 31;
    const int wid  = tid >> 5;
    const int bh   = blockIdx.x;
    const int qt   = blockIdx.y;
    const int b    = bh >> 4;
    const int h    = bh & 15;
    const int q0   = qt * 128;

    {
        const int e = tid >> 1, hf = tid & 1;
        const uint4* sh = (const uint4*)(g_kvbh + (size_t)bh*HD*HD + e*HD + hf*32);
        const uint4* sl = (const uint4*)(g_kvbl + (size_t)bh*HD*HD + e*HD + hf*32);
        #pragma unroll
        for(int i=0;i<4;i++){
            uint4 a_ = sh[i];
            uint4 c_ = sl[i];
            *(uint4*)&kvh[e*SP2 + hf*32 + i*8] = a_;
            *(uint4*)&kvl[e*SP2 + hf*32 + i*8] = c_;
        }
        if(tid < HD) sks[tid] = g_ks[(size_t)bh*HD + tid];
    }
    __syncthreads();

    {
        const int rg = tid >> 4;
        const int dq = tid & 15;
        const float* Qb = Q + ((size_t)(b*LQN + q0))*EMB + (size_t)h*HD;
        float4 ksv = *(float4*)&sks[dq*4];
        #pragma unroll
        for(int i=0;i<16;i++){
            const int row = i*8 + rg;
            float4 f = *(const float4*)(Qb + (size_t)row*EMB + dq*4);
            float p0=phi_sig(f.x), p1=phi_sig(f.y), p2=phi_sig(f.z), p3=phi_sig(f.w);
            float dp = fmaf(p0,ksv.x, fmaf(p1,ksv.y, fmaf(p2,ksv.z, p3*ksv.w)));
            u64 hv, lv;
            pack_hilo4(p0,p1,p2,p3, hv, lv);
            *(u64*)&qh[row*SP2 + dq*4] = hv;
            *(u64*)&ql[row*SP2 + dq*4] = lv;
            dp += __shfl_xor_sync(0xffffffffu, dp, 1);
            dp += __shfl_xor_sync(0xffffffffu, dp, 2);
            dp += __shfl_xor_sync(0xffffffffu, dp, 4);
            dp += __shfl_xor_sync(0xffffffffu, dp, 8);
            if(dq == 0) sden[row] = dp;
        }
    }
    __syncthreads();

    const u32 qhB = sm32(qh), qlB = sm32(ql), kvhB = sm32(kvh), kvlB = sm32(kvl);
    const u32 arow = (u32)(((lane&7) + ((lane>>3)&1)*8)*SP2 + ((lane>>4)&1)*8);
    u32 boff[4];
    #pragma unroll
    for(int g2=0; g2<4; g2++)
        boff[g2] = (u32)(((lane&7) + ((lane>>4)&1)*8 + g2*16)*SP2 + ((lane>>3)&1)*8);

    float acc[2][8][4];
    #pragma unroll
    for(int u_=0;u_<2;u_++)
        #pragma unroll
        for(int n=0;n<8;n++){ acc[u_][n][0]=acc[u_][n][1]=acc[u_][n][2]=acc[u_][n][3]=0.f; }

    #pragma unroll
    for(int s=0; s<4; s++){
        u32 Bh_[4][4], Bl_[4][4];
        #pragma unroll
        for(int g2=0; g2<4; g2++){
            ldm4(Bh_[g2], kvhB + (boff[g2] + s*16)*2);
            ldm4(Bl_[g2], kvlB + (boff[g2] + s*16)*2);
        }
        #pragma unroll
        for(int u_=0; u_<2; u_++){
            const u32 ab = (arow + (u32)((wid*32 + u_*16)*SP2) + s*16)*2;
            u32 ah[4], al[4];
            ldm4(ah, qhB + ab);
            ldm4(al, qlB + ab);
            #pragma unroll
            for(int g2=0; g2<4; g2++){
                mma_bf16(acc[u_][g2*2],   ah, Bh_[g2]);
                mma_bf16(acc[u_][g2*2],   al, Bh_[g2]);
                mma_bf16(acc[u_][g2*2],   ah, Bl_[g2]);
                mma_bf16(acc[u_][g2*2+1], ah, Bh_[g2]+2);
                mma_bf16(acc[u_][g2*2+1], al, Bh_[g2]+2);
                mma_bf16(acc[u_][g2*2+1], ah, Bl_[g2]+2);
            }
        }
    }

    // ---- NEW staged epilogue ----
    __syncthreads();                    // all warps done reading q planes
    float* stage = (float*)smp2;        // [128][OSTR] overlay on qh/ql
    {
        const int g  = lane >> 2;
        const int tg = lane & 3;
        #pragma unroll
        for(int u_=0; u_<2; u_++){
            const int qa = wid*32 + u_*16 + g;
            const int qb = qa + 8;
            const float rda = rcpf(sden[qa]);
            const float rdb = rcpf(sden[qb]);
            #pragma unroll
            for(int n=0;n<8;n++){
                const int e = n*8 + tg*2;
                *(float2*)&stage[qa*OSTR + e] = make_float2(acc[u_][n][0]*rda, acc[u_][n][1]*rda);
                *(float2*)&stage[qb*OSTR + e] = make_float2(acc[u_][n][2]*rdb, acc[u_][n][3]*rdb);
            }
        }
    }
    __syncthreads();
    {
        const int rg = tid >> 4;
        const int dq = tid & 15;
        float* ob = out + ((size_t)(b*LQN + q0))*EMB + (size_t)h*HD + dq*4;
        #pragma unroll
        for(int i=0;i<16;i++){
            const int row = i*8 + rg;
            float4 v = *(const float4*)&stage[row*OSTR + dq*4];
            *(float4*)(ob + (size_t)row*EMB) = v;
        }
    }
}

// ---------------- launch ----------------
extern "C" void kernel_launch(void* const* d_in, const int* in_sizes, int n_in,
                              void* d_out, int out_size){
    const float* Q = (const float*)d_in[0];
    const float* K = (const float*)d_in[1];
    const float* V = (const float*)d_in[2];
    float* out = (float*)d_out;

    const int smem2 = (2*128*SP2 + 2*64*SP2)*2 + (128 + 64)*4;
    cudaFuncSetAttribute(la_phase2, cudaFuncAttributeMaxDynamicSharedMemorySize, smem2);

    la_phase1<<<dim3(BHN, NCH2), 128>>>(K, V);
    la_reduce<<<BHN, 256>>>();
    la_phase2<<<dim3(BHN, LQN/128), 128, smem2>>>(Q, out);
}

// round 15
// speedup vs baseline: 1.0352x; 1.0352x over previous
#include <cuda_runtime.h>
#include <cuda_bf16.h>
#include <cstdint>
#include <cstddef>

#define BATCH  4
#define LQN    4096
#define LKN    4096
#define EMB    1024
#define NH     16
#define HD     64
#define BHN    64
#define NCH2   16       // phase1 chunks
#define KCH    256      // k rows per phase1 CTA
#define KT1    32       // k rows per phase1 tile
#define SP2    72       // phase2 plane stride (u16)

typedef unsigned long long u64;
typedef unsigned int u32;
typedef unsigned short u16;

// Scratch (static __device__ — no allocation)
__device__ float g_kvp[(size_t)NCH2*BHN*HD*HD];
__device__ float g_ksp[(size_t)NCH2*BHN*HD];
__device__ float g_ks [(size_t)BHN*HD];
__device__ u16   g_kvbh[(size_t)BHN*HD*HD];   // kv^T hi bf16 [bh][e][d]
__device__ u16   g_kvbl[(size_t)BHN*HD*HD];

// ---------------- helpers ----------------
__device__ __forceinline__ float phi_sig(float x){
    float t, r;
    float a = fmaf(x, -0.8732633f, 5.9179351f);
    asm("ex2.approx.ftz.f32 %0, %1;" : "=f"(t) : "f"(a));
    asm("rcp.approx.ftz.f32 %0, %1;" : "=f"(r) : "f"(1.0f + t));
    return r;
}
__device__ __forceinline__ float rcpf(float x){
    float r; asm("rcp.approx.ftz.f32 %0, %1;" : "=f"(r) : "f"(x)); return r;
}
__device__ __forceinline__ u32 sm32(const void* p){
    u32 a; asm("{ .reg .u64 t; cvta.to.shared.u64 t, %1; cvt.u32.u64 %0, t; }" : "=r"(a) : "l"(p));
    return a;
}
__device__ __forceinline__ void ldm4(u32* r, u32 addr){
    asm volatile("ldmatrix.sync.aligned.m8n8.x4.shared.b16 {%0,%1,%2,%3}, [%4];"
        : "=r"(r[0]),"=r"(r[1]),"=r"(r[2]),"=r"(r[3]) : "r"(addr));
}
__device__ __forceinline__ void ldm4t(u32* r, u32 addr){
    asm volatile("ldmatrix.sync.aligned.m8n8.x4.trans.shared.b16 {%0,%1,%2,%3}, [%4];"
        : "=r"(r[0]),"=r"(r[1]),"=r"(r[2]),"=r"(r[3]) : "r"(addr));
}
__device__ __forceinline__ void mma_bf16(float* c, const u32* a, const u32* b){
    asm volatile("mma.sync.aligned.m16n8k16.row.col.f32.bf16.bf16.f32 "
        "{%0,%1,%2,%3}, {%4,%5,%6,%7}, {%8,%9}, {%0,%1,%2,%3};"
        : "+f"(c[0]),"+f"(c[1]),"+f"(c[2]),"+f"(c[3])
        : "r"(a[0]),"r"(a[1]),"r"(a[2]),"r"(a[3]), "r"(b[0]),"r"(b[1]));
}
__device__ __forceinline__ void mma_b(float* c, const u32* a, u32 b0, u32 b1){
    asm volatile("mma.sync.aligned.m16n8k16.row.col.f32.bf16.bf16.f32 "
        "{%0,%1,%2,%3}, {%4,%5,%6,%7}, {%8,%9}, {%0,%1,%2,%3};"
        : "+f"(c[0]),"+f"(c[1]),"+f"(c[2]),"+f"(c[3])
        : "r"(a[0]),"r"(a[1]),"r"(a[2]),"r"(a[3]), "r"(b0),"r"(b1));
}
__device__ __forceinline__ void hilo2(float x0, float x1, u32& hp, u32& lp){
    __nv_bfloat16 h0 = __float2bfloat16_rn(x0);
    __nv_bfloat16 h1 = __float2bfloat16_rn(x1);
    float l0 = x0 - __bfloat162float(h0);
    float l1 = x1 - __bfloat162float(h1);
    __nv_bfloat16 q0 = __float2bfloat16_rn(l0);
    __nv_bfloat16 q1 = __float2bfloat16_rn(l1);
    hp = (u32)__bfloat16_as_ushort(h0) | ((u32)__bfloat16_as_ushort(h1) << 16);
    lp = (u32)__bfloat16_as_ushort(q0) | ((u32)__bfloat16_as_ushort(q1) << 16);
}
__device__ __forceinline__ void pack_hilo4(float p0,float p1,float p2,float p3,
                                           u64& hv, u64& lv){
    u32 h01, l01, h23, l23;
    hilo2(p0, p1, h01, l01);
    hilo2(p2, p3, h23, l23);
    hv = ((u64)h23 << 32) | (u64)h01;
    lv = ((u64)l23 << 32) | (u64)l01;
}

// ============================================================================
// Phase 1: kv = phi(K)^T @ V. Dual k-major swizzled planes + trans-ldmatrix
// (verified R13). NEW: 2x2 warp split (dh=wid>>1 -> d-half, eh=wid&1 ->
// e-half): halves cross-warp B-fragment redundancy; 8 ldm/s vs 10.
// grid (BHN, NCH2), 128 threads.
// ============================================================================
__global__ void __launch_bounds__(128, 4) la_phase1(const float* __restrict__ K,
                                                    const float* __restrict__ V){
    __shared__ __align__(16) unsigned char plK[2][8192];   // hi@0, lo@4096
    __shared__ __align__(16) unsigned char plV[2][8192];
    __shared__ float ksst[8][64];

    const int tid  = threadIdx.x;
    const int lane = tid & 31;
    const int wid  = tid >> 5;
    const int bh   = blockIdx.x;
    const int ck   = blockIdx.y;
    const int b    = bh >> 4;
    const int h    = bh & 15;
    const int k0   = ck * KCH;

    const float* Kb = K + (size_t)b*LKN*EMB + (size_t)h*HD;
    const float* Vb = V + (size_t)b*LKN*EMB + (size_t)h*HD;

    // coalesced loader: rows rg+8i, cols dq*4..+3
    const int rg = tid >> 4;
    const int dq = tid & 15;
    const u32 stoff = (u32)(((((dq>>1) ^ rg) & 7) << 4) + (dq&1)*8);

    // trans ldmatrix lane offsets (verified formula): rows (g3>>1)*8+j,
    // 16B-chunk (c + (g3&1)) ^ j
    const int j  = lane & 7;
    const int g3 = lane >> 3;
    const int rowpart = ((g3>>1)*8 + j)*128;
    const int dh = wid >> 1, eh = wid & 1;
    u32 oA[2], oB[2];
    #pragma unroll
    for(int m=0; m<2; m++)
        oA[m] = (u32)(rowpart + ((((dh*4 + m*2 + (g3&1)) ^ j) & 7) << 4));
    #pragma unroll
    for(int g2=0; g2<2; g2++)
        oB[g2] = (u32)(rowpart + ((((eh*4 + g2*2 + (g3&1)) ^ j) & 7) << 4));

    const u32 kbase = sm32(plK);
    const u32 vbase = sm32(plV);

    float acc[2][4][4];   // [m16 tile][n8 group: g2*2+half][frag]
    #pragma unroll
    for(int m=0;m<2;m++)
        #pragma unroll
        for(int n=0;n<4;n++){ acc[m][n][0]=acc[m][n][1]=acc[m][n][2]=acc[m][n][3]=0.f; }
    float ks4[4] = {0.f,0.f,0.f,0.f};

    float4 kf[4], vf[4];
    #pragma unroll
    for(int i=0;i<4;i++){
        kf[i] = *(const float4*)(Kb + (size_t)(k0 + rg + i*8)*EMB + dq*4);
        vf[i] = *(const float4*)(Vb + (size_t)(k0 + rg + i*8)*EMB + dq*4);
    }

    int st = 0;
    const int NT = KCH / KT1;
    for(int t=0; t<NT; t++){
        __syncthreads();
        {
            unsigned char* ks_ = &plK[st][0];
            unsigned char* vs_ = &plV[st][0];
            #pragma unroll
            for(int i=0;i<4;i++){
                const u32 off = (u32)((rg + i*8)*128) + stoff;
                float p0=phi_sig(kf[i].x), p1=phi_sig(kf[i].y),
                      p2=phi_sig(kf[i].z), p3=phi_sig(kf[i].w);
                ks4[0]+=p0; ks4[1]+=p1; ks4[2]+=p2; ks4[3]+=p3;
                u64 hv, lv;
                pack_hilo4(p0,p1,p2,p3, hv, lv);
                *(u64*)(ks_ + off)        = hv;
                *(u64*)(ks_ + 4096 + off) = lv;
                pack_hilo4(vf[i].x, vf[i].y, vf[i].z, vf[i].w, hv, lv);
                *(u64*)(vs_ + off)        = hv;
                *(u64*)(vs_ + 4096 + off) = lv;
            }
        }
        __syncthreads();
        if(t+1 < NT){
            const int kb = k0 + (t+1)*KT1;
            #pragma unroll
            for(int i=0;i<4;i++){
                kf[i] = *(const float4*)(Kb + (size_t)(kb + rg + i*8)*EMB + dq*4);
                vf[i] = *(const float4*)(Vb + (size_t)(kb + rg + i*8)*EMB + dq*4);
            }
        }
        #pragma unroll
        for(int s=0; s<2; s++){
            const u32 khi = kbase + (u32)(st*8192 + s*2048);
            const u32 vhi = vbase + (u32)(st*8192 + s*2048);
            u32 ah[2][4], al[2][4];
            #pragma unroll
            for(int m=0;m<2;m++){
                ldm4t(ah[m], khi + oA[m]);
                ldm4t(al[m], khi + 4096u + oA[m]);
            }
            #pragma unroll
            for(int g2=0; g2<2; g2++){
                u32 bh4[4], bl4[4];
                ldm4t(bh4, vhi + oB[g2]);
                ldm4t(bl4, vhi + 4096u + oB[g2]);
                #pragma unroll
                for(int m=0;m<2;m++){
                    mma_b(acc[m][g2*2],   ah[m], bh4[0], bh4[2]);
                    mma_b(acc[m][g2*2],   al[m], bh4[0], bh4[2]);
                    mma_b(acc[m][g2*2],   ah[m], bl4[0], bl4[2]);
                    mma_b(acc[m][g2*2+1], ah[m], bh4[1], bh4[3]);
                    mma_b(acc[m][g2*2+1], al[m], bh4[1], bh4[3]);
                    mma_b(acc[m][g2*2+1], ah[m], bl4[1], bl4[3]);
                }
            }
        }
        st ^= 1;
    }

    // write fp32 kv partial: d rows dh*32 + m*16 + {g, g+8}; e = eh*32 + n*8 + tg*2
    {
        float* gp = g_kvp + ((size_t)(ck*BHN + bh))*HD*HD;
        const int g  = lane >> 2;
        const int tg = lane & 3;
        #pragma unroll
        for(int m=0;m<2;m++){
            const int r0 = dh*32 + m*16 + g;
            const int r1 = r0 + 8;
            #pragma unroll
            for(int n=0;n<4;n++){
                const int e = eh*32 + n*8 + tg*2;
                *(float2*)(gp + (size_t)r0*HD + e) = make_float2(acc[m][n][0], acc[m][n][1]);
                *(float2*)(gp + (size_t)r1*HD + e) = make_float2(acc[m][n][2], acc[m][n][3]);
            }
        }
    }
    // ksum partial
    #pragma unroll
    for(int i=0;i<4;i++) ksst[rg][dq*4+i] = ks4[i];
    __syncthreads();
    if(tid < HD){
        float s = 0.f;
        #pragma unroll
        for(int i=0;i<8;i++) s += ksst[i][tid];
        g_ksp[(size_t)(ck*BHN + bh)*HD + tid] = s;
    }
}

// ============================================================================
// Reduce (VERIFIED R6)
// ============================================================================
__global__ void __launch_bounds__(256) la_reduce(){
    const int bh  = blockIdx.x;
    const int tid = threadIdx.x;
    for(int idx = tid; idx < HD*HD; idx += 256){
        float s = 0.f;
        #pragma unroll
        for(int c=0;c<NCH2;c++)
            s += g_kvp[((size_t)c*BHN + bh)*HD*HD + idx];
        const int d = idx >> 6, e = idx & 63;
        __nv_bfloat16 hi = __float2bfloat16_rn(s);
        __nv_bfloat16 lo = __float2bfloat16_rn(s - __bfloat162float(hi));
        g_kvbh[(size_t)bh*HD*HD + e*HD + d] = __bfloat16_as_ushort(hi);
        g_kvbl[(size_t)bh*HD*HD + e*HD + d] = __bfloat16_as_ushort(lo);
    }
    if(tid < HD){
        float s = 0.f;
        #pragma unroll
        for(int c=0;c<NCH2;c++)
            s += g_ksp[(size_t)(c*BHN + bh)*HD + tid];
        g_ks[(size_t)bh*HD + tid] = s;
    }
}

// ============================================================================
// Phase 2 (VERIFIED R13): cooperative conversion + R6 mma + direct epilogue.
// ============================================================================
extern __shared__ u16 smp2[];
__global__ void __launch_bounds__(128, 4) la_phase2(const float* __restrict__ Q,
                                                    float* __restrict__ out){
    u16* qh  = smp2;
    u16* ql  = qh  + 128*SP2;
    u16* kvh = ql  + 128*SP2;
    u16* kvl = kvh + 64*SP2;
    float* sden = (float*)(kvl + 64*SP2);
    float* sks  = sden + 128;

    const int tid  = threadIdx.x;
    const int lane = tid & 31;
    const int wid  = tid >> 5;
    const int bh   = blockIdx.x;
    const int qt   = blockIdx.y;
    const int b    = bh >> 4;
    const int h    = bh & 15;
    const int q0   = qt * 128;

    {
        const int e = tid >> 1, hf = tid & 1;
        const uint4* sh = (const uint4*)(g_kvbh + (size_t)bh*HD*HD + e*HD + hf*32);
        const uint4* sl = (const uint4*)(g_kvbl + (size_t)bh*HD*HD + e*HD + hf*32);
        #pragma unroll
        for(int i=0;i<4;i++){
            uint4 a_ = sh[i];
            uint4 c_ = sl[i];
            *(uint4*)&kvh[e*SP2 + hf*32 + i*8] = a_;
            *(uint4*)&kvl[e*SP2 + hf*32 + i*8] = c_;
        }
        if(tid < HD) sks[tid] = g_ks[(size_t)bh*HD + tid];
    }
    __syncthreads();

    {
        const int rg = tid >> 4;
        const int dq = tid & 15;
        const float* Qb = Q + ((size_t)(b*LQN + q0))*EMB + (size_t)h*HD;
        float4 ksv = *(float4*)&sks[dq*4];
        #pragma unroll
        for(int i=0;i<16;i++){
            const int row = i*8 + rg;
            float4 f = *(const float4*)(Qb + (size_t)row*EMB + dq*4);
            float p0=phi_sig(f.x), p1=phi_sig(f.y), p2=phi_sig(f.z), p3=phi_sig(f.w);
            float dp = fmaf(p0,ksv.x, fmaf(p1,ksv.y, fmaf(p2,ksv.z, p3*ksv.w)));
            u64 hv, lv;
            pack_hilo4(p0,p1,p2,p3, hv, lv);
            *(u64*)&qh[row*SP2 + dq*4] = hv;
            *(u64*)&ql[row*SP2 + dq*4] = lv;
            dp += __shfl_xor_sync(0xffffffffu, dp, 1);
            dp += __shfl_xor_sync(0xffffffffu, dp, 2);
            dp += __shfl_xor_sync(0xffffffffu, dp, 4);
            dp += __shfl_xor_sync(0xffffffffu, dp, 8);
            if(dq == 0) sden[row] = dp;
        }
    }
    __syncthreads();

    const u32 qhB = sm32(qh), qlB = sm32(ql), kvhB = sm32(kvh), kvlB = sm32(kvl);
    const u32 arow = (u32)(((lane&7) + ((lane>>3)&1)*8)*SP2 + ((lane>>4)&1)*8);
    u32 boff[4];
    #pragma unroll
    for(int g2=0; g2<4; g2++)
        boff[g2] = (u32)(((lane&7) + ((lane>>4)&1)*8 + g2*16)*SP2 + ((lane>>3)&1)*8);

    float acc[2][8][4];
    #pragma unroll
    for(int u_=0;u_<2;u_++)
        #pragma unroll
        for(int n=0;n<8;n++){ acc[u_][n][0]=acc[u_][n][1]=acc[u_][n][2]=acc[u_][n][3]=0.f; }

    #pragma unroll
    for(int s=0; s<4; s++){
        u32 Bh_[4][4], Bl_[4][4];
        #pragma unroll
        for(int g2=0; g2<4; g2++){
            ldm4(Bh_[g2], kvhB + (boff[g2] + s*16)*2);
            ldm4(Bl_[g2], kvlB + (boff[g2] + s*16)*2);
        }
        #pragma unroll
        for(int u_=0; u_<2; u_++){
            const u32 ab = (arow + (u32)((wid*32 + u_*16)*SP2) + s*16)*2;
            u32 ah[4], al[4];
            ldm4(ah, qhB + ab);
            ldm4(al, qlB + ab);
            #pragma unroll
            for(int g2=0; g2<4; g2++){
                mma_bf16(acc[u_][g2*2],   ah, Bh_[g2]);
                mma_bf16(acc[u_][g2*2],   al, Bh_[g2]);
                mma_bf16(acc[u_][g2*2],   ah, Bl_[g2]);
                mma_bf16(acc[u_][g2*2+1], ah, Bh_[g2]+2);
                mma_bf16(acc[u_][g2*2+1], al, Bh_[g2]+2);
                mma_bf16(acc[u_][g2*2+1], ah, Bl_[g2]+2);
            }
        }
    }

    {
        const int g  = lane >> 2;
        const int tg = lane & 3;
        #pragma unroll
        for(int u_=0; u_<2; u_++){
            const int qa = wid*32 + u_*16 + g;
            const int qb = qa + 8;
            const float rda = rcpf(sden[qa]);
            const float rdb = rcpf(sden[qb]);
            float* ra = out + ((size_t)(b*LQN + q0 + qa))*EMB + (size_t)h*HD;
            float* rb = out + ((size_t)(b*LQN + q0 + qb))*EMB + (size_t)h*HD;
            #pragma unroll
            for(int n=0;n<8;n++){
                const int e = n*8 + tg*2;
                *(float2*)(ra + e) = make_float2(acc[u_][n][0]*rda, acc[u_][n][1]*rda);
                *(float2*)(rb + e) = make_float2(acc[u_][n][2]*rdb, acc[u_][n][3]*rdb);
            }
        }
    }
}

// ---------------- launch ----------------
extern "C" void kernel_launch(void* const* d_in, const int* in_sizes, int n_in,
                              void* d_out, int out_size){
    const float* Q = (const float*)d_in[0];
    const float* K = (const float*)d_in[1];
    const float* V = (const float*)d_in[2];
    float* out = (float*)d_out;

    const int smem2 = (2*128*SP2 + 2*64*SP2)*2 + (128 + 64)*4;
    cudaFuncSetAttribute(la_phase2, cudaFuncAttributeMaxDynamicSharedMemorySize, smem2);

    la_phase1<<<dim3(BHN, NCH2), 128>>>(K, V);
    la_reduce<<<BHN, 256>>>();
    la_phase2<<<dim3(BHN, LQN/128), 128, smem2>>>(Q, out);
}

// round 16
// speedup vs baseline: 1.0551x; 1.0193x over previous
#include <cuda_runtime.h>
#include <cuda_bf16.h>
#include <cstdint>
#include <cstddef>

#define BATCH  4
#define LQN    4096
#define LKN    4096
#define EMB    1024
#define NH     16
#define HD     64
#define BHN    64
#define NCH2   8        // phase1 chunks (R16: 16 -> 8; single clean wave)
#define KCH    512      // k rows per phase1 CTA
#define KT1    32       // k rows per phase1 tile
#define SP2    72       // phase2 plane stride (u16)

typedef unsigned long long u64;
typedef unsigned int u32;
typedef unsigned short u16;

// Scratch (static __device__ — no allocation)
__device__ float g_kvp[(size_t)NCH2*BHN*HD*HD];
__device__ float g_ksp[(size_t)NCH2*BHN*HD];
__device__ float g_ks [(size_t)BHN*HD];
__device__ u16   g_kvbh[(size_t)BHN*HD*HD];   // kv^T hi bf16 [bh][e][d]
__device__ u16   g_kvbl[(size_t)BHN*HD*HD];

// ---------------- helpers ----------------
__device__ __forceinline__ float phi_sig(float x){
    float t, r;
    float a = fmaf(x, -0.8732633f, 5.9179351f);
    asm("ex2.approx.ftz.f32 %0, %1;" : "=f"(t) : "f"(a));
    asm("rcp.approx.ftz.f32 %0, %1;" : "=f"(r) : "f"(1.0f + t));
    return r;
}
__device__ __forceinline__ float rcpf(float x){
    float r; asm("rcp.approx.ftz.f32 %0, %1;" : "=f"(r) : "f"(x)); return r;
}
__device__ __forceinline__ u32 sm32(const void* p){
    u32 a; asm("{ .reg .u64 t; cvta.to.shared.u64 t, %1; cvt.u32.u64 %0, t; }" : "=r"(a) : "l"(p));
    return a;
}
__device__ __forceinline__ void ldm4(u32* r, u32 addr){
    asm volatile("ldmatrix.sync.aligned.m8n8.x4.shared.b16 {%0,%1,%2,%3}, [%4];"
        : "=r"(r[0]),"=r"(r[1]),"=r"(r[2]),"=r"(r[3]) : "r"(addr));
}
__device__ __forceinline__ void ldm4t(u32* r, u32 addr){
    asm volatile("ldmatrix.sync.aligned.m8n8.x4.trans.shared.b16 {%0,%1,%2,%3}, [%4];"
        : "=r"(r[0]),"=r"(r[1]),"=r"(r[2]),"=r"(r[3]) : "r"(addr));
}
__device__ __forceinline__ void mma_bf16(float* c, const u32* a, const u32* b){
    asm volatile("mma.sync.aligned.m16n8k16.row.col.f32.bf16.bf16.f32 "
        "{%0,%1,%2,%3}, {%4,%5,%6,%7}, {%8,%9}, {%0,%1,%2,%3};"
        : "+f"(c[0]),"+f"(c[1]),"+f"(c[2]),"+f"(c[3])
        : "r"(a[0]),"r"(a[1]),"r"(a[2]),"r"(a[3]), "r"(b[0]),"r"(b[1]));
}
__device__ __forceinline__ void mma_b(float* c, const u32* a, u32 b0, u32 b1){
    asm volatile("mma.sync.aligned.m16n8k16.row.col.f32.bf16.bf16.f32 "
        "{%0,%1,%2,%3}, {%4,%5,%6,%7}, {%8,%9}, {%0,%1,%2,%3};"
        : "+f"(c[0]),"+f"(c[1]),"+f"(c[2]),"+f"(c[3])
        : "r"(a[0]),"r"(a[1]),"r"(a[2]),"r"(a[3]), "r"(b0),"r"(b1));
}
__device__ __forceinline__ void hilo2(float x0, float x1, u32& hp, u32& lp){
    __nv_bfloat16 h0 = __float2bfloat16_rn(x0);
    __nv_bfloat16 h1 = __float2bfloat16_rn(x1);
    float l0 = x0 - __bfloat162float(h0);
    float l1 = x1 - __bfloat162float(h1);
    __nv_bfloat16 q0 = __float2bfloat16_rn(l0);
    __nv_bfloat16 q1 = __float2bfloat16_rn(l1);
    hp = (u32)__bfloat16_as_ushort(h0) | ((u32)__bfloat16_as_ushort(h1) << 16);
    lp = (u32)__bfloat16_as_ushort(q0) | ((u32)__bfloat16_as_ushort(q1) << 16);
}
__device__ __forceinline__ void pack_hilo4(float p0,float p1,float p2,float p3,
                                           u64& hv, u64& lv){
    u32 h01, l01, h23, l23;
    hilo2(p0, p1, h01, l01);
    hilo2(p2, p3, h23, l23);
    hv = ((u64)h23 << 32) | (u64)h01;
    lv = ((u64)l23 << 32) | (u64)l01;
}

// ============================================================================
// Phase 1 (structure VERIFIED R13/R15): kv = phi(K)^T @ V, dual k-major
// swizzled planes + trans-ldmatrix, 2x2 warp split. R16: KCH=512 (NT=16).
// grid (BHN, NCH2), 128 threads.
// ============================================================================
__global__ void __launch_bounds__(128, 4) la_phase1(const float* __restrict__ K,
                                                    const float* __restrict__ V){
    __shared__ __align__(16) unsigned char plK[2][8192];   // hi@0, lo@4096
    __shared__ __align__(16) unsigned char plV[2][8192];
    __shared__ float ksst[8][64];

    const int tid  = threadIdx.x;
    const int lane = tid & 31;
    const int wid  = tid >> 5;
    const int bh   = blockIdx.x;
    const int ck   = blockIdx.y;
    const int b    = bh >> 4;
    const int h    = bh & 15;
    const int k0   = ck * KCH;

    const float* Kb = K + (size_t)b*LKN*EMB + (size_t)h*HD;
    const float* Vb = V + (size_t)b*LKN*EMB + (size_t)h*HD;

    // coalesced loader: rows rg+8i, cols dq*4..+3
    const int rg = tid >> 4;
    const int dq = tid & 15;
    const u32 stoff = (u32)(((((dq>>1) ^ rg) & 7) << 4) + (dq&1)*8);

    // trans ldmatrix lane offsets (verified): rows (g3>>1)*8+j, chunk (c+(g3&1))^j
    const int j  = lane & 7;
    const int g3 = lane >> 3;
    const int rowpart = ((g3>>1)*8 + j)*128;
    const int dh = wid >> 1, eh = wid & 1;
    u32 oA[2], oB[2];
    #pragma unroll
    for(int m=0; m<2; m++)
        oA[m] = (u32)(rowpart + ((((dh*4 + m*2 + (g3&1)) ^ j) & 7) << 4));
    #pragma unroll
    for(int g2=0; g2<2; g2++)
        oB[g2] = (u32)(rowpart + ((((eh*4 + g2*2 + (g3&1)) ^ j) & 7) << 4));

    const u32 kbase = sm32(plK);
    const u32 vbase = sm32(plV);

    float acc[2][4][4];
    #pragma unroll
    for(int m=0;m<2;m++)
        #pragma unroll
        for(int n=0;n<4;n++){ acc[m][n][0]=acc[m][n][1]=acc[m][n][2]=acc[m][n][3]=0.f; }
    float ks4[4] = {0.f,0.f,0.f,0.f};

    float4 kf[4], vf[4];
    #pragma unroll
    for(int i=0;i<4;i++){
        kf[i] = *(const float4*)(Kb + (size_t)(k0 + rg + i*8)*EMB + dq*4);
        vf[i] = *(const float4*)(Vb + (size_t)(k0 + rg + i*8)*EMB + dq*4);
    }

    int st = 0;
    const int NT = KCH / KT1;   // 16
    for(int t=0; t<NT; t++){
        __syncthreads();
        {
            unsigned char* ks_ = &plK[st][0];
            unsigned char* vs_ = &plV[st][0];
            #pragma unroll
            for(int i=0;i<4;i++){
                const u32 off = (u32)((rg + i*8)*128) + stoff;
                float p0=phi_sig(kf[i].x), p1=phi_sig(kf[i].y),
                      p2=phi_sig(kf[i].z), p3=phi_sig(kf[i].w);
                ks4[0]+=p0; ks4[1]+=p1; ks4[2]+=p2; ks4[3]+=p3;
                u64 hv, lv;
                pack_hilo4(p0,p1,p2,p3, hv, lv);
                *(u64*)(ks_ + off)        = hv;
                *(u64*)(ks_ + 4096 + off) = lv;
                pack_hilo4(vf[i].x, vf[i].y, vf[i].z, vf[i].w, hv, lv);
                *(u64*)(vs_ + off)        = hv;
                *(u64*)(vs_ + 4096 + off) = lv;
            }
        }
        __syncthreads();
        if(t+1 < NT){
            const int kb = k0 + (t+1)*KT1;
            #pragma unroll
            for(int i=0;i<4;i++){
                kf[i] = *(const float4*)(Kb + (size_t)(kb + rg + i*8)*EMB + dq*4);
                vf[i] = *(const float4*)(Vb + (size_t)(kb + rg + i*8)*EMB + dq*4);
            }
        }
        #pragma unroll
        for(int s=0; s<2; s++){
            const u32 khi = kbase + (u32)(st*8192 + s*2048);
            const u32 vhi = vbase + (u32)(st*8192 + s*2048);
            u32 ah[2][4], al[2][4];
            #pragma unroll
            for(int m=0;m<2;m++){
                ldm4t(ah[m], khi + oA[m]);
                ldm4t(al[m], khi + 4096u + oA[m]);
            }
            #pragma unroll
            for(int g2=0; g2<2; g2++){
                u32 bh4[4], bl4[4];
                ldm4t(bh4, vhi + oB[g2]);
                ldm4t(bl4, vhi + 4096u + oB[g2]);
                #pragma unroll
                for(int m=0;m<2;m++){
                    mma_b(acc[m][g2*2],   ah[m], bh4[0], bh4[2]);
                    mma_b(acc[m][g2*2],   al[m], bh4[0], bh4[2]);
                    mma_b(acc[m][g2*2],   ah[m], bl4[0], bl4[2]);
                    mma_b(acc[m][g2*2+1], ah[m], bh4[1], bh4[3]);
                    mma_b(acc[m][g2*2+1], al[m], bh4[1], bh4[3]);
                    mma_b(acc[m][g2*2+1], ah[m], bl4[1], bl4[3]);
                }
            }
        }
        st ^= 1;
    }

    // write fp32 kv partial
    {
        float* gp = g_kvp + ((size_t)(ck*BHN + bh))*HD*HD;
        const int g  = lane >> 2;
        const int tg = lane & 3;
        #pragma unroll
        for(int m=0;m<2;m++){
            const int r0 = dh*32 + m*16 + g;
            const int r1 = r0 + 8;
            #pragma unroll
            for(int n=0;n<4;n++){
                const int e = eh*32 + n*8 + tg*2;
                *(float2*)(gp + (size_t)r0*HD + e) = make_float2(acc[m][n][0], acc[m][n][1]);
                *(float2*)(gp + (size_t)r1*HD + e) = make_float2(acc[m][n][2], acc[m][n][3]);
            }
        }
    }
    // ksum partial
    #pragma unroll
    for(int i=0;i<4;i++) ksst[rg][dq*4+i] = ks4[i];
    __syncthreads();
    if(tid < HD){
        float s = 0.f;
        #pragma unroll
        for(int i=0;i<8;i++) s += ksst[i][tid];
        g_ksp[(size_t)(ck*BHN + bh)*HD + tid] = s;
    }
}

// ============================================================================
// Reduce (VERIFIED R6; NCH2=8)
// ============================================================================
__global__ void __launch_bounds__(256) la_reduce(){
    const int bh  = blockIdx.x;
    const int tid = threadIdx.x;
    for(int idx = tid; idx < HD*HD; idx += 256){
        float s = 0.f;
        #pragma unroll
        for(int c=0;c<NCH2;c++)
            s += g_kvp[((size_t)c*BHN + bh)*HD*HD + idx];
        const int d = idx >> 6, e = idx & 63;
        __nv_bfloat16 hi = __float2bfloat16_rn(s);
        __nv_bfloat16 lo = __float2bfloat16_rn(s - __bfloat162float(hi));
        g_kvbh[(size_t)bh*HD*HD + e*HD + d] = __bfloat16_as_ushort(hi);
        g_kvbl[(size_t)bh*HD*HD + e*HD + d] = __bfloat16_as_ushort(lo);
    }
    if(tid < HD){
        float s = 0.f;
        #pragma unroll
        for(int c=0;c<NCH2;c++)
            s += g_ksp[(size_t)(c*BHN + bh)*HD + tid];
        g_ks[(size_t)bh*HD + tid] = s;
    }
}

// ============================================================================
// Phase 2 (VERIFIED R13): cooperative conversion + R6 mma + direct epilogue.
// ============================================================================
extern __shared__ u16 smp2[];
__global__ void __launch_bounds__(128, 4) la_phase2(const float* __restrict__ Q,
                                                    float* __restrict__ out){
    u16* qh  = smp2;
    u16* ql  = qh  + 128*SP2;
    u16* kvh = ql  + 128*SP2;
    u16* kvl = kvh + 64*SP2;
    float* sden = (float*)(kvl + 64*SP2);
    float* sks  = sden + 128;

    const int tid  = threadIdx.x;
    const int lane = tid & 31;
    const int wid  = tid >> 5;
    const int bh   = blockIdx.x;
    const int qt   = blockIdx.y;
    const int b    = bh >> 4;
    const int h    = bh & 15;
    const int q0   = qt * 128;

    {
        const int e = tid >> 1, hf = tid & 1;
        const uint4* sh = (const uint4*)(g_kvbh + (size_t)bh*HD*HD + e*HD + hf*32);
        const uint4* sl = (const uint4*)(g_kvbl + (size_t)bh*HD*HD + e*HD + hf*32);
        #pragma unroll
        for(int i=0;i<4;i++){
            uint4 a_ = sh[i];
            uint4 c_ = sl[i];
            *(uint4*)&kvh[e*SP2 + hf*32 + i*8] = a_;
            *(uint4*)&kvl[e*SP2 + hf*32 + i*8] = c_;
        }
        if(tid < HD) sks[tid] = g_ks[(size_t)bh*HD + tid];
    }
    __syncthreads();

    {
        const int rg = tid >> 4;
        const int dq = tid & 15;
        const float* Qb = Q + ((size_t)(b*LQN + q0))*EMB + (size_t)h*HD;
        float4 ksv = *(float4*)&sks[dq*4];
        #pragma unroll
        for(int i=0;i<16;i++){
            const int row = i*8 + rg;
            float4 f = *(const float4*)(Qb + (size_t)row*EMB + dq*4);
            float p0=phi_sig(f.x), p1=phi_sig(f.y), p2=phi_sig(f.z), p3=phi_sig(f.w);
            float dp = fmaf(p0,ksv.x, fmaf(p1,ksv.y, fmaf(p2,ksv.z, p3*ksv.w)));
            u64 hv, lv;
            pack_hilo4(p0,p1,p2,p3, hv, lv);
            *(u64*)&qh[row*SP2 + dq*4] = hv;
            *(u64*)&ql[row*SP2 + dq*4] = lv;
            dp += __shfl_xor_sync(0xffffffffu, dp, 1);
            dp += __shfl_xor_sync(0xffffffffu, dp, 2);
            dp += __shfl_xor_sync(0xffffffffu, dp, 4);
            dp += __shfl_xor_sync(0xffffffffu, dp, 8);
            if(dq == 0) sden[row] = dp;
        }
    }
    __syncthreads();

    const u32 qhB = sm32(qh), qlB = sm32(ql), kvhB = sm32(kvh), kvlB = sm32(kvl);
    const u32 arow = (u32)(((lane&7) + ((lane>>3)&1)*8)*SP2 + ((lane>>4)&1)*8);
    u32 boff[4];
    #pragma unroll
    for(int g2=0; g2<4; g2++)
        boff[g2] = (u32)(((lane&7) + ((lane>>4)&1)*8 + g2*16)*SP2 + ((lane>>3)&1)*8);

    float acc[2][8][4];
    #pragma unroll
    for(int u_=0;u_<2;u_++)
        #pragma unroll
        for(int n=0;n<8;n++){ acc[u_][n][0]=acc[u_][n][1]=acc[u_][n][2]=acc[u_][n][3]=0.f; }

    #pragma unroll
    for(int s=0; s<4; s++){
        u32 Bh_[4][4], Bl_[4][4];
        #pragma unroll
        for(int g2=0; g2<4; g2++){
            ldm4(Bh_[g2], kvhB + (boff[g2] + s*16)*2);
            ldm4(Bl_[g2], kvlB + (boff[g2] + s*16)*2);
        }
        #pragma unroll
        for(int u_=0; u_<2; u_++){
            const u32 ab = (arow + (u32)((wid*32 + u_*16)*SP2) + s*16)*2;
            u32 ah[4], al[4];
            ldm4(ah, qhB + ab);
            ldm4(al, qlB + ab);
            #pragma unroll
            for(int g2=0; g2<4; g2++){
                mma_bf16(acc[u_][g2*2],   ah, Bh_[g2]);
                mma_bf16(acc[u_][g2*2],   al, Bh_[g2]);
                mma_bf16(acc[u_][g2*2],   ah, Bl_[g2]);
                mma_bf16(acc[u_][g2*2+1], ah, Bh_[g2]+2);
                mma_bf16(acc[u_][g2*2+1], al, Bh_[g2]+2);
                mma_bf16(acc[u_][g2*2+1], ah, Bl_[g2]+2);
            }
        }
    }

    {
        const int g  = lane >> 2;
        const int tg = lane & 3;
        #pragma unroll
        for(int u_=0; u_<2; u_++){
            const int qa = wid*32 + u_*16 + g;
            const int qb = qa + 8;
            const float rda = rcpf(sden[qa]);
            const float rdb = rcpf(sden[qb]);
            float* ra = out + ((size_t)(b*LQN + q0 + qa))*EMB + (size_t)h*HD;
            float* rb = out + ((size_t)(b*LQN + q0 + qb))*EMB + (size_t)h*HD;
            #pragma unroll
            for(int n=0;n<8;n++){
                const int e = n*8 + tg*2;
                *(float2*)(ra + e) = make_float2(acc[u_][n][0]*rda, acc[u_][n][1]*rda);
                *(float2*)(rb + e) = make_float2(acc[u_][n][2]*rdb, acc[u_][n][3]*rdb);
            }
        }
    }
}

// ---------------- launch ----------------
extern "C" void kernel_launch(void* const* d_in, const int* in_sizes, int n_in,
                              void* d_out, int out_size){
    const float* Q = (const float*)d_in[0];
    const float* K = (const float*)d_in[1];
    const float* V = (const float*)d_in[2];
    float* out = (float*)d_out;

    const int smem2 = (2*128*SP2 + 2*64*SP2)*2 + (128 + 64)*4;
    cudaFuncSetAttribute(la_phase2, cudaFuncAttributeMaxDynamicSharedMemorySize, smem2);

    la_phase1<<<dim3(BHN, NCH2), 128>>>(K, V);
    la_reduce<<<BHN, 256>>>();
    la_phase2<<<dim3(BHN, LQN/128), 128, smem2>>>(Q, out);
}